// round 6
// baseline (speedup 1.0000x reference)
#include <cuda_runtime.h>
#include <cuda_bf16.h>
#include <math.h>
#include <stdint.h>

#define NN 100000
#define EE 200000
#define GG 4096
#define DD 300
#define HH 600
#define LL 5
#define DECH 1200
#define MAXO 1783
// padded K dims (multiples of 64)
#define KPD 320
#define KPH 640
#define KPDEC 1216

// ---------------- scratch (device globals) ----------------
__device__ float g_h [(size_t)NN*DD];
__device__ float g_z [(size_t)NN*DD];
__device__ float g_y [(size_t)NN*HH];
__device__ float g_stats[2*DECH];
__device__ float g_scale[DECH];
__device__ float g_shift[DECH];
__device__ unsigned g_hg[(size_t)GG*DD];
__device__ float g_d [(size_t)GG*HH];
__device__ float g_dz[(size_t)GG*DECH];
// bf16 hi/lo activation planes
__device__ __nv_bfloat16 g_zh[(size_t)NN*KPD],  g_zl[(size_t)NN*KPD];
__device__ __nv_bfloat16 g_yh[(size_t)NN*KPH],  g_yl[(size_t)NN*KPH];
__device__ __nv_bfloat16 g_sh[(size_t)GG*KPD],  g_sl[(size_t)GG*KPD];
__device__ __nv_bfloat16 g_muh[(size_t)GG*KPD], g_mul[(size_t)GG*KPD];
__device__ __nv_bfloat16 g_dzh[(size_t)GG*KPDEC], g_dzl[(size_t)GG*KPDEC];
// bf16 hi/lo transposed weights
__device__ __nv_bfloat16 g_w1th[(size_t)LL*HH*KPD],   g_w1tl[(size_t)LL*HH*KPD];
__device__ __nv_bfloat16 g_w2th[(size_t)LL*DD*KPH],   g_w2tl[(size_t)LL*DD*KPH];
__device__ __nv_bfloat16 g_dwth[(size_t)HH*KPD],      g_dwtl[(size_t)HH*KPD];
__device__ __nv_bfloat16 g_d1th[(size_t)6*DECH*KPD],  g_d1tl[(size_t)6*DECH*KPD];
__device__ __nv_bfloat16 g_d2th[(size_t)6*MAXO*KPDEC], g_d2tl[(size_t)6*MAXO*KPDEC];

// ================= helpers =================
__device__ __forceinline__ uint32_t smem_u32(const void* p) {
    uint32_t a;
    asm("{ .reg .u64 t; cvta.to.shared.u64 t, %1; cvt.u32.u64 %0, t; }" : "=r"(a) : "l"(p));
    return a;
}
__device__ __forceinline__ void split_bf(float v, __nv_bfloat16& h, __nv_bfloat16& l) {
    h = __float2bfloat16(v);
    l = __float2bfloat16(v - __bfloat162float(h));
}
#define LDSM_X4(r, a) \
    asm volatile("ldmatrix.sync.aligned.m8n8.x4.shared.b16 {%0,%1,%2,%3}, [%4];" \
        : "=r"((r)[0]), "=r"((r)[1]), "=r"((r)[2]), "=r"((r)[3]) : "r"(a))
__device__ __forceinline__ void mma_bf16(float* c, const uint32_t* a, const uint32_t* b) {
    asm volatile("mma.sync.aligned.m16n8k16.row.col.f32.bf16.bf16.f32 "
        "{%0,%1,%2,%3}, {%4,%5,%6,%7}, {%8,%9}, {%0,%1,%2,%3};"
        : "+f"(c[0]), "+f"(c[1]), "+f"(c[2]), "+f"(c[3])
        : "r"(a[0]), "r"(a[1]), "r"(a[2]), "r"(a[3]), "r"(b[0]), "r"(b[1]));
}
__device__ __forceinline__ void cpa16(uint32_t dst, const void* src, int bytes) {
    asm volatile("cp.async.cg.shared.global [%0], [%1], 16, %2;"
        :: "r"(dst), "l"(src), "r"(bytes) : "memory");
}
#define CPA_COMMIT() asm volatile("cp.async.commit_group;" ::: "memory")
#define CPA_WAIT1()  asm volatile("cp.async.wait_group 1;" ::: "memory")

// ================= HMMA GEMM =================
// C[M x Nc] = A[M x Kp] @ Bt[Nc x Kp]^T + bias; A,B as bf16 hi/lo planes.
// 3-product hi/lo split, fp32 accumulate, cp.async 3-stage pipeline.
// CTA tile 128x128, TK=64; warp tile 32x64 (8 warps).
#define TM 128
#define TN 128
#define TK 64
#define PITCH 72                 // bf16 elems per smem row (144B; bank shift 4/row)
#define ARR_B 18432              // 128 rows x 144B
#define STAGE_B 73728
#define GEMM_SMEM (3 * STAGE_B)

__global__ void __launch_bounds__(256, 1) k_tgemm(
    const __nv_bfloat16* __restrict__ Ah, const __nv_bfloat16* __restrict__ Al, int lda,
    const __nv_bfloat16* __restrict__ Bh, const __nv_bfloat16* __restrict__ Bl, int ldb,
    const float* __restrict__ bias,
    float* __restrict__ C, int ldc,
    int M, int Nc, int Kp,
    float* __restrict__ stats, int do_stats)
{
    extern __shared__ char smem[];
    uint32_t sbase = smem_u32(smem);
    int tid = threadIdx.x, wid = tid >> 5, lane = tid & 31;
    int row0 = blockIdx.y * TM;
    int col0 = blockIdx.x * TN;
    int wm = wid & 3, wn = wid >> 2;     // warp: rows wm*32..+31, cols wn*64..+63

    float acc[2][8][4];
#pragma unroll
    for (int i = 0; i < 2; i++)
#pragma unroll
        for (int j = 0; j < 8; j++)
#pragma unroll
            for (int q = 0; q < 4; q++) acc[i][j][q] = 0.f;

    int nt = Kp / TK;

#define LOADST(T, BUF) do { \
    int kt = (T) * TK; \
    uint32_t sst = sbase + (uint32_t)(BUF) * STAGE_B; \
    _Pragma("unroll") \
    for (int q = 0; q < 18; q++) { \
        int chunk = tid + q * 256; \
        int arr = chunk / 1152; \
        int rem = chunk - arr * 1152; \
        int r = rem / 9; \
        int c9 = rem - r * 9; \
        uint32_t dst = sst + (uint32_t)(arr * ARR_B + r * 144 + c9 * 16); \
        const __nv_bfloat16* base; int gr, ld, lim; \
        if (arr == 0)      { base = Ah; gr = row0 + r; ld = lda; lim = M; } \
        else if (arr == 1) { base = Al; gr = row0 + r; ld = lda; lim = M; } \
        else if (arr == 2) { base = Bh; gr = col0 + r; ld = ldb; lim = Nc; } \
        else               { base = Bl; gr = col0 + r; ld = ldb; lim = Nc; } \
        int ok = (gr < lim && c9 < 8) ? 16 : 0; \
        int grc = (gr < lim) ? gr : 0; \
        int gc = kt + ((c9 < 8) ? c9 * 8 : 0); \
        cpa16(dst, base + (size_t)grc * ld + gc, ok); \
    } } while (0)

    LOADST(0, 0); CPA_COMMIT();
    LOADST(1, 1); CPA_COMMIT();

    // fragment addressing
    int a_r = lane & 15;                 // rows within 16
    int a_c = (lane >> 4) << 3;          // 0 or 8 (k)
    int b_r = (lane & 7) + ((lane & 16) >> 1);   // col-row within 16
    int b_c = ((lane >> 3) & 1) << 3;    // 0 or 8 (k)

    for (int t = 0; t < nt; t++) {
        CPA_WAIT1();
        __syncthreads();
        int buf = t % 3;
        uint32_t sA = sbase + (uint32_t)buf * STAGE_B;
        uint32_t sB = sA + 2 * ARR_B;
#pragma unroll
        for (int kk = 0; kk < TK; kk += 16) {
            uint32_t ah[2][4], al[2][4], bh[16], bl[16];
#pragma unroll
            for (int i = 0; i < 2; i++) {
                uint32_t ad = sA + (uint32_t)((wm * 32 + i * 16 + a_r) * PITCH + kk + a_c) * 2;
                LDSM_X4(ah[i], ad);
                LDSM_X4(al[i], ad + ARR_B);
            }
#pragma unroll
            for (int jj = 0; jj < 4; jj++) {
                uint32_t bd = sB + (uint32_t)((wn * 64 + jj * 16 + b_r) * PITCH + kk + b_c) * 2;
                LDSM_X4(&bh[jj * 4], bd);
                LDSM_X4(&bl[jj * 4], bd + ARR_B);
            }
#pragma unroll
            for (int i = 0; i < 2; i++)
#pragma unroll
                for (int j = 0; j < 8; j++) {
                    mma_bf16(acc[i][j], ah[i], &bh[j * 2]);
                    mma_bf16(acc[i][j], ah[i], &bl[j * 2]);
                    mma_bf16(acc[i][j], al[i], &bh[j * 2]);
                }
        }
        if (t + 2 < nt) { LOADST(t + 2, (t + 2) % 3); }
        CPA_COMMIT();
    }
#undef LOADST

    // ---- epilogue: bias + store + stats ----
    int g = lane >> 2, t4 = lane & 3;
#pragma unroll
    for (int i = 0; i < 2; i++) {
        int r0c = row0 + wm * 32 + i * 16 + g;
        bool rv0 = (r0c < M), rv1 = (r0c + 8 < M);
#pragma unroll
        for (int j = 0; j < 8; j++) {
            int c0c = col0 + wn * 64 + j * 8 + t4 * 2;
            bool cv0 = (c0c < Nc), cv1 = (c0c + 1 < Nc);
            float b0 = cv0 ? bias[c0c] : 0.f;
            float b1 = cv1 ? bias[c0c + 1] : 0.f;
            float v0 = acc[i][j][0] + b0, v1 = acc[i][j][1] + b1;
            float v2 = acc[i][j][2] + b0, v3 = acc[i][j][3] + b1;
            if (rv0 && cv0) C[(size_t)r0c * ldc + c0c] = v0;
            if (rv0 && cv1) C[(size_t)r0c * ldc + c0c + 1] = v1;
            if (rv1 && cv0) C[(size_t)(r0c + 8) * ldc + c0c] = v2;
            if (rv1 && cv1) C[(size_t)(r0c + 8) * ldc + c0c + 1] = v3;
            acc[i][j][0] = (rv0 && cv0) ? v0 : 0.f;
            acc[i][j][1] = (rv0 && cv1) ? v1 : 0.f;
            acc[i][j][2] = (rv1 && cv0) ? v2 : 0.f;
            acc[i][j][3] = (rv1 && cv1) ? v3 : 0.f;
        }
    }
    if (do_stats) {
#pragma unroll
        for (int j = 0; j < 8; j++) {
            float se = 0.f, so = 0.f, qe = 0.f, qo = 0.f;
#pragma unroll
            for (int i = 0; i < 2; i++) {
                float v0 = acc[i][j][0], v1 = acc[i][j][1];
                float v2 = acc[i][j][2], v3 = acc[i][j][3];
                se += v0 + v2; so += v1 + v3;
                qe += v0 * v0 + v2 * v2; qo += v1 * v1 + v3 * v3;
            }
#pragma unroll
            for (int off = 4; off < 32; off <<= 1) {
                se += __shfl_xor_sync(0xffffffffu, se, off);
                so += __shfl_xor_sync(0xffffffffu, so, off);
                qe += __shfl_xor_sync(0xffffffffu, qe, off);
                qo += __shfl_xor_sync(0xffffffffu, qo, off);
            }
            if (lane < 4) {
                int ce = col0 + wn * 64 + j * 8 + lane * 2;
                if (ce < Nc)     { atomicAdd(&stats[ce], se);     atomicAdd(&stats[Nc + ce], qe); }
                if (ce + 1 < Nc) { atomicAdd(&stats[ce + 1], so); atomicAdd(&stats[Nc + ce + 1], qo); }
            }
        }
    }
}

// ============ weight transpose + hi/lo convert (batched) ============
__global__ void k_wcvt(const float* __restrict__ in,
                       __nv_bfloat16* __restrict__ hi, __nv_bfloat16* __restrict__ lo,
                       int K, int N, int Kp) {
    __shared__ float t[32][33];
    int b = blockIdx.z;
    const float* I = in + (size_t)b * K * N;
    __nv_bfloat16* H = hi + (size_t)b * N * Kp;
    __nv_bfloat16* L = lo + (size_t)b * N * Kp;
    int r0 = blockIdx.y * 32, c0 = blockIdx.x * 32;
    int c = c0 + threadIdx.x;
#pragma unroll
    for (int i = 0; i < 32; i += 8) {
        int r = r0 + threadIdx.y + i;
        t[threadIdx.y + i][threadIdx.x] = (r < K && c < N) ? I[(size_t)r * N + c] : 0.f;
    }
    __syncthreads();
    int k = r0 + threadIdx.x;
#pragma unroll
    for (int i = 0; i < 32; i += 8) {
        int n = c0 + threadIdx.y + i;
        if (n < N && k < Kp) {
            float v = t[threadIdx.x][threadIdx.y + i];
            __nv_bfloat16 h, l; split_bf(v, h, l);
            H[(size_t)n * Kp + k] = h;
            L[(size_t)n * Kp + k] = l;
        }
    }
}

__global__ void k_cvtpad(const float* __restrict__ in,
                         __nv_bfloat16* __restrict__ hi, __nv_bfloat16* __restrict__ lo,
                         long total, int C, int Cp) {
    long i = (long)blockIdx.x * blockDim.x + threadIdx.x;
    if (i >= total) return;
    int n = (int)(i / Cp), c = (int)(i - (long)n * Cp);
    float v = (c < C) ? in[(size_t)n * C + c] : 0.f;
    __nv_bfloat16 h, l; split_bf(v, h, l);
    hi[i] = h; lo[i] = l;
}

__global__ void k_bnact_cvt(const float* __restrict__ X,
                            const float* __restrict__ scale, const float* __restrict__ shift,
                            __nv_bfloat16* __restrict__ hi, __nv_bfloat16* __restrict__ lo,
                            long total, int C, int Cp, int gelu) {
    long i = (long)blockIdx.x * blockDim.x + threadIdx.x;
    if (i >= total) return;
    int n = (int)(i / Cp), c = (int)(i - (long)n * Cp);
    float r = 0.f;
    if (c < C) {
        float v = X[(size_t)n * C + c] * scale[c] + shift[c];
        r = gelu ? (0.5f * v * (1.f + erff(v * 0.70710678118654752f))) : fmaxf(v, 0.f);
    }
    __nv_bfloat16 h, l; split_bf(r, h, l);
    hi[i] = h; lo[i] = l;
}

// ================= elementwise =================
__global__ void k_zero(float* p, int n) {
    int i = blockIdx.x * blockDim.x + threadIdx.x;
    if (i < n) p[i] = 0.f;
}
__global__ void k_zero_u(unsigned* p, int n) {
    int i = blockIdx.x * blockDim.x + threadIdx.x;
    if (i < n) p[i] = 0u;
}
__global__ void k_init_h4(const float4* __restrict__ atom_emb, const int* __restrict__ x_idx,
                          float4* __restrict__ h) {
    long i = (long)blockIdx.x * blockDim.x + threadIdx.x;
    const int C4 = DD / 4;
    long total = (long)NN * C4;
    if (i >= total) return;
    int n = (int)(i / C4);
    int d = (int)(i - (long)n * C4);
    h[i] = atom_emb[(size_t)x_idx[n] * C4 + d];
}
__global__ void k_init_z4(const float4* __restrict__ h, const float* __restrict__ epsp,
                          float4* __restrict__ z) {
    long i = (long)blockIdx.x * blockDim.x + threadIdx.x;
    long total = (long)NN * (DD / 4);
    if (i >= total) return;
    float e = 1.f + *epsp;
    float4 v = h[i];
    z[i] = make_float4(e * v.x, e * v.y, e * v.z, e * v.w);
}
__global__ void k_edge4(const float4* __restrict__ h, const float4* __restrict__ ee,
                        const int* __restrict__ attr, const int* __restrict__ ei,
                        float* __restrict__ z) {
    long i = (long)blockIdx.x * blockDim.x + threadIdx.x;
    const int C4 = DD / 4;
    long total = (long)EE * C4;
    if (i >= total) return;
    int e = (int)(i / C4);
    int q = (int)(i - (long)e * C4);
    int src = ei[e];
    int dst = ei[EE + e];
    float4 a = h[(size_t)src * C4 + q];
    float4 b = ee[(size_t)attr[e] * C4 + q];
    float m0 = a.x + b.x, m1 = a.y + b.y, m2 = a.z + b.z, m3 = a.w + b.w;
    float* zp = z + (size_t)dst * DD + q * 4;
    if (m0 > 0.f) atomicAdd(zp + 0, m0);
    if (m1 > 0.f) atomicAdd(zp + 1, m1);
    if (m2 > 0.f) atomicAdd(zp + 2, m2);
    if (m3 > 0.f) atomicAdd(zp + 3, m3);
}
__global__ void k_bn_final(const float* __restrict__ sums, float invM, int C,
                           const float* __restrict__ gamma, const float* __restrict__ beta,
                           float* __restrict__ scale, float* __restrict__ shift) {
    int c = blockIdx.x * blockDim.x + threadIdx.x;
    if (c >= C) return;
    float mean = sums[c] * invM;
    float var  = sums[C + c] * invM - mean * mean;
    float istd = rsqrtf(var + 1e-5f);
    float sc = istd * gamma[c];
    scale[c] = sc;
    shift[c] = beta[c] - mean * sc;
}
__global__ void k_bn_apply4(float4* __restrict__ X, float4* __restrict__ res,
                            const float4* __restrict__ scale, const float4* __restrict__ shift,
                            long total4, int C4, int mode) {
    long i = (long)blockIdx.x * blockDim.x + threadIdx.x;
    if (i >= total4) return;
    int c = (int)(i % C4);
    float4 x = X[i], sc = scale[c], sh = shift[c];
    float v0 = x.x * sc.x + sh.x, v1 = x.y * sc.y + sh.y;
    float v2 = x.z * sc.z + sh.z, v3 = x.w * sc.w + sh.w;
    float4 r = res[i];
    if (mode == 1) {
        res[i] = make_float4(r.x + fmaxf(v0, 0.f), r.y + fmaxf(v1, 0.f),
                             r.z + fmaxf(v2, 0.f), r.w + fmaxf(v3, 0.f));
    } else {
        res[i] = make_float4(r.x + v0, r.y + v1, r.z + v2, r.w + v3);
    }
}
__device__ __forceinline__ unsigned enc_f(float x) {
    unsigned u = __float_as_uint(x);
    return (u & 0x80000000u) ? ~u : (u | 0x80000000u);
}
__global__ void k_segmax(const float* __restrict__ h, const int* __restrict__ batch,
                         unsigned* __restrict__ hg) {
    long i = (long)blockIdx.x * blockDim.x + threadIdx.x;
    long total = (long)NN * DD;
    if (i >= total) return;
    int n = (int)(i / DD);
    int d = (int)(i - (long)n * DD);
    atomicMax(&hg[(size_t)batch[n] * DD + d], enc_f(h[i]));
}
__global__ void k_silu_cvt(const unsigned* __restrict__ hg,
                           __nv_bfloat16* __restrict__ hi, __nv_bfloat16* __restrict__ lo,
                           long total, int C, int Cp) {
    long i = (long)blockIdx.x * blockDim.x + threadIdx.x;
    if (i >= total) return;
    int n = (int)(i / Cp), c = (int)(i - (long)n * Cp);
    float r = 0.f;
    if (c < C) {
        unsigned u = hg[(size_t)n * C + c];
        u = (u & 0x80000000u) ? (u & 0x7fffffffu) : ~u;
        float x = __uint_as_float(u);
        r = x / (1.f + expf(-x));
    }
    __nv_bfloat16 h, l; split_bf(r, h, l);
    hi[i] = h; lo[i] = l;
}
__global__ void k_split(const float* __restrict__ d, float* __restrict__ out, long offS) {
    long i = (long)blockIdx.x * blockDim.x + threadIdx.x;
    long total = (long)GG * HH;
    if (i >= total) return;
    int g = (int)(i / HH);
    int c = (int)(i - (long)g * HH);
    float v = d[i];
    if (c < DD) {
        out[(size_t)g * DD + c] = v;
    } else {
        float sp = fmaxf(v, 0.f) + log1pf(expf(-fabsf(v))) + 1e-7f;
        out[offS + (size_t)g * DD + (c - DD)] = sp;
    }
}

// ================= host side =================
static void tgemm(const __nv_bfloat16* Ah, const __nv_bfloat16* Al, int lda,
                  const __nv_bfloat16* Bh, const __nv_bfloat16* Bl, int ldb,
                  const float* bias, float* C, int ldc,
                  int M, int Nc, int Kp, float* stats, int do_stats) {
    dim3 gr((Nc + TN - 1) / TN, (M + TM - 1) / TM);
    k_tgemm<<<gr, 256, GEMM_SMEM>>>(Ah, Al, lda, Bh, Bl, ldb, bias, C, ldc, M, Nc, Kp, stats, do_stats);
}
static void wcvt(const float* in, __nv_bfloat16* hi, __nv_bfloat16* lo,
                 int K, int N, int Kp, int B) {
    dim3 bl(32, 8), gr((N + 31) / 32, (Kp + 31) / 32, B);
    k_wcvt<<<gr, bl>>>(in, hi, lo, K, N, Kp);
}

extern "C" void kernel_launch(void* const* d_in, const int* in_sizes, int n_in,
                              void* d_out, int out_size) {
    const float* atom_emb   = (const float*)d_in[0];
    const float* edge_emb   = (const float*)d_in[1];
    const float* eps        = (const float*)d_in[2];
    const float* conv_w1    = (const float*)d_in[3];
    const float* conv_b1    = (const float*)d_in[4];
    const float* conv_bn1_g = (const float*)d_in[5];
    const float* conv_bn1_b = (const float*)d_in[6];
    const float* conv_w2    = (const float*)d_in[7];
    const float* conv_b2    = (const float*)d_in[8];
    const float* bn_g       = (const float*)d_in[9];
    const float* bn_b       = (const float*)d_in[10];
    const float* dist_w     = (const float*)d_in[11];
    const float* dist_b     = (const float*)d_in[12];
    const float* dec_w1     = (const float*)d_in[13];
    const float* dec_b1     = (const float*)d_in[14];
    const float* dec_bn_g   = (const float*)d_in[15];
    const float* dec_bn_b   = (const float*)d_in[16];
    const float* dec_w2     = (const float*)d_in[17];
    const float* dec_b2     = (const float*)d_in[18];
    const int*   x_idx      = (const int*)d_in[19];
    const int*   edge_attr  = (const int*)d_in[20];
    const int*   edge_index = (const int*)d_in[21];
    const int*   batch      = (const int*)d_in[22];
    float* out = (float*)d_out;

    cudaFuncSetAttribute(k_tgemm, cudaFuncAttributeMaxDynamicSharedMemorySize, GEMM_SMEM);

    float *h, *z, *y, *stats, *scale, *shift, *dbuf, *dz;
    unsigned* hg;
    __nv_bfloat16 *zh, *zl, *yh, *yl, *sh, *sl, *muh, *mul, *dzh, *dzl;
    __nv_bfloat16 *w1th, *w1tl, *w2th, *w2tl, *dwth, *dwtl, *d1th, *d1tl, *d2th, *d2tl;
    cudaGetSymbolAddress((void**)&h,     g_h);
    cudaGetSymbolAddress((void**)&z,     g_z);
    cudaGetSymbolAddress((void**)&y,     g_y);
    cudaGetSymbolAddress((void**)&stats, g_stats);
    cudaGetSymbolAddress((void**)&scale, g_scale);
    cudaGetSymbolAddress((void**)&shift, g_shift);
    cudaGetSymbolAddress((void**)&hg,    g_hg);
    cudaGetSymbolAddress((void**)&dbuf,  g_d);
    cudaGetSymbolAddress((void**)&dz,    g_dz);
    cudaGetSymbolAddress((void**)&zh,    g_zh);   cudaGetSymbolAddress((void**)&zl,  g_zl);
    cudaGetSymbolAddress((void**)&yh,    g_yh);   cudaGetSymbolAddress((void**)&yl,  g_yl);
    cudaGetSymbolAddress((void**)&sh,    g_sh);   cudaGetSymbolAddress((void**)&sl,  g_sl);
    cudaGetSymbolAddress((void**)&muh,   g_muh);  cudaGetSymbolAddress((void**)&mul, g_mul);
    cudaGetSymbolAddress((void**)&dzh,   g_dzh);  cudaGetSymbolAddress((void**)&dzl, g_dzl);
    cudaGetSymbolAddress((void**)&w1th,  g_w1th); cudaGetSymbolAddress((void**)&w1tl, g_w1tl);
    cudaGetSymbolAddress((void**)&w2th,  g_w2th); cudaGetSymbolAddress((void**)&w2tl, g_w2tl);
    cudaGetSymbolAddress((void**)&dwth,  g_dwth); cudaGetSymbolAddress((void**)&dwtl, g_dwtl);
    cudaGetSymbolAddress((void**)&d1th,  g_d1th); cudaGetSymbolAddress((void**)&d1tl, g_d1tl);
    cudaGetSymbolAddress((void**)&d2th,  g_d2th); cudaGetSymbolAddress((void**)&d2tl, g_d2tl);

    // transpose + convert weights once per call
    wcvt(conv_w1, w1th, w1tl, DD, HH, KPD, LL);
    wcvt(conv_w2, w2th, w2tl, HH, DD, KPH, LL);
    wcvt(dist_w,  dwth, dwtl, DD, HH, KPD, 1);
    wcvt(dec_w1,  d1th, d1tl, DD, DECH, KPD, 6);
    wcvt(dec_w2,  d2th, d2tl, DECH, MAXO, KPDEC, 6);

    const long ND  = (long)NN * DD;
    const long ND4 = ND / 4;
    const long ED4 = (long)EE * DD / 4;
    const long NZP = (long)NN * KPD;
    const long NYP = (long)NN * KPH;

    k_init_h4<<<(int)((ND4 + 255) / 256), 256>>>((const float4*)atom_emb, x_idx, (float4*)h);

    for (int l = 0; l < LL; l++) {
        k_init_z4<<<(int)((ND4 + 255) / 256), 256>>>((const float4*)h, eps + l, (float4*)z);
        k_edge4<<<(int)((ED4 + 255) / 256), 256>>>((const float4*)h,
                 (const float4*)(edge_emb + (size_t)l * 5 * DD), edge_attr, edge_index, z);
        k_cvtpad<<<(int)((NZP + 255) / 256), 256>>>(z, zh, zl, NZP, DD, KPD);
        k_zero<<<(2 * HH + 255) / 256, 256>>>(stats, 2 * HH);
        tgemm(zh, zl, KPD, w1th + (size_t)l * HH * KPD, w1tl + (size_t)l * HH * KPD, KPD,
              conv_b1 + (size_t)l * HH, y, HH, NN, HH, KPD, stats, 1);
        k_bn_final<<<(HH + 255) / 256, 256>>>(stats, 1.f / (float)NN, HH,
              conv_bn1_g + (size_t)l * HH, conv_bn1_b + (size_t)l * HH, scale, shift);
        k_bnact_cvt<<<(int)((NYP + 255) / 256), 256>>>(y, scale, shift, yh, yl, NYP, HH, KPH, 0);
        k_zero<<<(2 * DD + 255) / 256, 256>>>(stats, 2 * DD);
        tgemm(yh, yl, KPH, w2th + (size_t)l * DD * KPH, w2tl + (size_t)l * DD * KPH, KPH,
              conv_b2 + (size_t)l * DD, z, DD, NN, DD, KPH, stats, 1);
        k_bn_final<<<(DD + 255) / 256, 256>>>(stats, 1.f / (float)NN, DD,
              bn_g + (size_t)l * DD, bn_b + (size_t)l * DD, scale, shift);
        k_bn_apply4<<<(int)((ND4 + 255) / 256), 256>>>((float4*)z, (float4*)h,
              (const float4*)scale, (const float4*)shift, ND4, DD / 4, (l < LL - 1) ? 1 : 2);
    }

    // pooling -> silu -> bf16
    int GD = GG * DD;
    const long GSP = (long)GG * KPD;
    k_zero_u<<<(GD + 255) / 256, 256>>>(hg, GD);
    k_segmax<<<(int)((ND + 255) / 256), 256>>>(h, batch, hg);
    k_silu_cvt<<<(int)((GSP + 255) / 256), 256>>>(hg, sh, sl, GSP, DD, KPD);

    // d = silu(h_graph) @ dist_w + dist_b
    tgemm(sh, sl, KPD, dwth, dwtl, KPD, dist_b, dbuf, HH, GG, HH, KPD, stats, 0);

    const long OFF_SG = (long)GG * DD;
    k_split<<<(int)(((long)GG * HH + 255) / 256), 256>>>(dbuf, out, OFF_SG);
    k_cvtpad<<<(int)((GSP + 255) / 256), 256>>>(out, muh, mul, GSP, DD, KPD);

    const long OFF_O0   = 2L * GG * DD;
    const long OFF_GENE = OFF_O0 + (long)GG * 1024;
    const long OFF_CELL = OFF_GENE + (long)GG * 1973;
    const long OFF_O5   = OFF_CELL + (long)GG * 2749;
    const int  dims[6] = {1024, 1111, 862, 1783, 966, 978};
    const long base[6] = {OFF_O0, OFF_GENE, OFF_GENE + 1111, OFF_CELL, OFF_CELL + 1783, OFF_O5};
    const int  ldcs[6] = {1024, 1973, 1973, 2749, 2749, 978};

    const long GDP = (long)GG * KPDEC;
    for (int i = 0; i < 6; i++) {
        k_zero<<<(2 * DECH + 255) / 256, 256>>>(stats, 2 * DECH);
        tgemm(muh, mul, KPD, d1th + (size_t)i * DECH * KPD, d1tl + (size_t)i * DECH * KPD, KPD,
              dec_b1 + (size_t)i * DECH, dz, DECH, GG, DECH, KPD, stats, 1);
        k_bn_final<<<(DECH + 255) / 256, 256>>>(stats, 1.f / (float)GG, DECH,
              dec_bn_g + (size_t)i * DECH, dec_bn_b + (size_t)i * DECH, scale, shift);
        k_bnact_cvt<<<(int)((GDP + 255) / 256), 256>>>(dz, scale, shift, dzh, dzl, GDP, DECH, KPDEC, 1);
        tgemm(dzh, dzl, KPDEC, d2th + (size_t)i * MAXO * KPDEC, d2tl + (size_t)i * MAXO * KPDEC, KPDEC,
              dec_b2 + (size_t)i * MAXO, out + base[i], ldcs[i], GG, dims[i], KPDEC, stats, 0);
    }
}

// round 7
// speedup vs baseline: 1.0780x; 1.0780x over previous
#include <cuda_runtime.h>
#include <cuda_bf16.h>
#include <math.h>
#include <stdint.h>

#define NN 100000
#define EE 200000
#define GG 4096
#define DD 300
#define HH 600
#define LL 5
#define DECH 1200
#define MAXO 1783
// padded K dims (multiples of 32)
#define KPD 320
#define KPH 608
#define KPDEC 1216

// ---------------- scratch (device globals) ----------------
__device__ float g_h [(size_t)NN*DD];
__device__ float g_z [(size_t)NN*DD];
__device__ float g_y [(size_t)NN*HH];
__device__ float g_stats[2*DECH];
__device__ float g_scale[DECH];
__device__ float g_shift[DECH];
__device__ unsigned g_hg[(size_t)GG*DD];
__device__ float g_d [(size_t)GG*HH];
__device__ float g_dz[(size_t)GG*DECH];
// bf16 hi/lo activation planes
__device__ __nv_bfloat16 g_zh[(size_t)NN*KPD],  g_zl[(size_t)NN*KPD];
__device__ __nv_bfloat16 g_yh[(size_t)NN*KPH],  g_yl[(size_t)NN*KPH];
__device__ __nv_bfloat16 g_sh[(size_t)GG*KPD],  g_sl[(size_t)GG*KPD];
__device__ __nv_bfloat16 g_muh[(size_t)GG*KPD], g_mul[(size_t)GG*KPD];
__device__ __nv_bfloat16 g_dzh[(size_t)GG*KPDEC], g_dzl[(size_t)GG*KPDEC];
// bf16 hi/lo transposed weights
__device__ __nv_bfloat16 g_w1th[(size_t)LL*HH*KPD],   g_w1tl[(size_t)LL*HH*KPD];
__device__ __nv_bfloat16 g_w2th[(size_t)LL*DD*KPH],   g_w2tl[(size_t)LL*DD*KPH];
__device__ __nv_bfloat16 g_dwth[(size_t)HH*KPD],      g_dwtl[(size_t)HH*KPD];
__device__ __nv_bfloat16 g_d1th[(size_t)6*DECH*KPD],  g_d1tl[(size_t)6*DECH*KPD];
__device__ __nv_bfloat16 g_d2th[(size_t)6*MAXO*KPDEC], g_d2tl[(size_t)6*MAXO*KPDEC];

// ================= helpers =================
__device__ __forceinline__ uint32_t smem_u32(const void* p) {
    uint32_t a;
    asm("{ .reg .u64 t; cvta.to.shared.u64 t, %1; cvt.u32.u64 %0, t; }" : "=r"(a) : "l"(p));
    return a;
}
__device__ __forceinline__ void split_bf(float v, __nv_bfloat16& h, __nv_bfloat16& l) {
    h = __float2bfloat16(v);
    l = __float2bfloat16(v - __bfloat162float(h));
}
#define LDSM_X4(r, a) \
    asm volatile("ldmatrix.sync.aligned.m8n8.x4.shared.b16 {%0,%1,%2,%3}, [%4];" \
        : "=r"((r)[0]), "=r"((r)[1]), "=r"((r)[2]), "=r"((r)[3]) : "r"(a))
#define LDSM_X2(r, a) \
    asm volatile("ldmatrix.sync.aligned.m8n8.x2.shared.b16 {%0,%1}, [%2];" \
        : "=r"((r)[0]), "=r"((r)[1]) : "r"(a))
__device__ __forceinline__ void mma_bf16(float* c, const uint32_t* a, const uint32_t* b) {
    asm volatile("mma.sync.aligned.m16n8k16.row.col.f32.bf16.bf16.f32 "
        "{%0,%1,%2,%3}, {%4,%5,%6,%7}, {%8,%9}, {%0,%1,%2,%3};"
        : "+f"(c[0]), "+f"(c[1]), "+f"(c[2]), "+f"(c[3])
        : "r"(a[0]), "r"(a[1]), "r"(a[2]), "r"(a[3]), "r"(b[0]), "r"(b[1]));
}
__device__ __forceinline__ void cpa16(uint32_t dst, const void* src, int bytes) {
    asm volatile("cp.async.cg.shared.global [%0], [%1], 16, %2;"
        :: "r"(dst), "l"(src), "r"(bytes) : "memory");
}
#define CPA_COMMIT() asm volatile("cp.async.commit_group;" ::: "memory")
#define CPA_WAIT0()  asm volatile("cp.async.wait_group 0;" ::: "memory")

// ================= HMMA GEMM =================
// C[M x Nc] = A[M x Kp] @ Bt[Nc x Kp]^T + bias; A,B as bf16 hi/lo planes.
// 3-product hi/lo split, fp32 accumulate, 2-stage cp.async, 2 CTAs/SM.
#define TM 128
#define TN 128
#define TK 32
#define PITCH 40                 // bf16 elems per smem row (80B)
#define ARR_B 10240              // 128 rows x 80B
#define STAGE_B 40960
#define GEMM_SMEM (2 * STAGE_B)

__global__ void __launch_bounds__(256, 2) k_tgemm(
    const __nv_bfloat16* __restrict__ Ah, const __nv_bfloat16* __restrict__ Al, int lda,
    const __nv_bfloat16* __restrict__ Bh, const __nv_bfloat16* __restrict__ Bl, int ldb,
    const float* __restrict__ bias,
    float* __restrict__ C, int ldc,
    int M, int Nc, int Kp,
    float* __restrict__ stats, int do_stats)
{
    extern __shared__ char smem[];
    uint32_t sbase = smem_u32(smem);
    int tid = threadIdx.x, wid = tid >> 5, lane = tid & 31;
    int row0 = blockIdx.y * TM;
    int col0 = blockIdx.x * TN;
    int wm = wid & 1, wn = wid >> 1;     // warp tile: rows wm*64, cols wn*32

    float acc[4][4][4];
#pragma unroll
    for (int i = 0; i < 4; i++)
#pragma unroll
        for (int j = 0; j < 4; j++)
#pragma unroll
            for (int q = 0; q < 4; q++) acc[i][j][q] = 0.f;

    int nt = Kp / TK;

#define LOADST(T, BUF) do { \
    int kt = (T) * TK; \
    uint32_t sst = sbase + (uint32_t)(BUF) * STAGE_B; \
    _Pragma("unroll") \
    for (int q = 0; q < 8; q++) { \
        int w = tid + (q & 1) * 256; \
        int r = w >> 2, k8 = w & 3; \
        int arr = q >> 1; \
        uint32_t dst = sst + (uint32_t)(arr * ARR_B + r * 80 + k8 * 16); \
        const __nv_bfloat16* base; int gr, ld, lim; \
        if (arr == 0)      { base = Ah; gr = row0 + r; ld = lda; lim = M; } \
        else if (arr == 1) { base = Al; gr = row0 + r; ld = lda; lim = M; } \
        else if (arr == 2) { base = Bh; gr = col0 + r; ld = ldb; lim = Nc; } \
        else               { base = Bl; gr = col0 + r; ld = ldb; lim = Nc; } \
        int ok = (gr < lim) ? 16 : 0; \
        int grc = (gr < lim) ? gr : 0; \
        cpa16(dst, base + (size_t)grc * ld + kt + k8 * 8, ok); \
    } } while (0)

    LOADST(0, 0); CPA_COMMIT();

    int a_r = lane & 15;
    int a_c = (lane >> 4) << 3;
    int b_r = lane & 7;
    int b_c = ((lane >> 3) & 1) << 3;

    for (int t = 0; t < nt; t++) {
        CPA_WAIT0();
        __syncthreads();
        int buf = t & 1;
        // issue next stage into the other buffer (its readers finished before the sync)
        if (t + 1 < nt) { LOADST(t + 1, buf ^ 1); }
        CPA_COMMIT();

        uint32_t sA = sbase + (uint32_t)buf * STAGE_B;
        uint32_t sB = sA + 2 * ARR_B;
#pragma unroll
        for (int kk = 0; kk < TK; kk += 16) {
            uint32_t ah[4][4], al[4][4], bh[4][2], bl[4][2];
#pragma unroll
            for (int i = 0; i < 4; i++) {
                uint32_t ad = sA + (uint32_t)((wm * 64 + i * 16 + a_r) * PITCH + kk + a_c) * 2;
                LDSM_X4(ah[i], ad);
                LDSM_X4(al[i], ad + ARR_B);
            }
#pragma unroll
            for (int j = 0; j < 4; j++) {
                uint32_t bd = sB + (uint32_t)((wn * 32 + j * 8 + b_r) * PITCH + kk + b_c) * 2;
                LDSM_X2(bh[j], bd);
                LDSM_X2(bl[j], bd + ARR_B);
            }
#pragma unroll
            for (int i = 0; i < 4; i++)
#pragma unroll
                for (int j = 0; j < 4; j++) {
                    mma_bf16(acc[i][j], ah[i], bh[j]);
                    mma_bf16(acc[i][j], ah[i], bl[j]);
                    mma_bf16(acc[i][j], al[i], bh[j]);
                }
        }
    }
#undef LOADST

    // ---- epilogue: bias + store + stats ----
    int g = lane >> 2, t4 = lane & 3;
#pragma unroll
    for (int i = 0; i < 4; i++) {
        int r0c = row0 + wm * 64 + i * 16 + g;
        bool rv0 = (r0c < M), rv1 = (r0c + 8 < M);
#pragma unroll
        for (int j = 0; j < 4; j++) {
            int c0c = col0 + wn * 32 + j * 8 + t4 * 2;
            bool cv0 = (c0c < Nc), cv1 = (c0c + 1 < Nc);
            float b0 = cv0 ? bias[c0c] : 0.f;
            float b1 = cv1 ? bias[c0c + 1] : 0.f;
            float v0 = acc[i][j][0] + b0, v1 = acc[i][j][1] + b1;
            float v2 = acc[i][j][2] + b0, v3 = acc[i][j][3] + b1;
            if (rv0 && cv0) C[(size_t)r0c * ldc + c0c] = v0;
            if (rv0 && cv1) C[(size_t)r0c * ldc + c0c + 1] = v1;
            if (rv1 && cv0) C[(size_t)(r0c + 8) * ldc + c0c] = v2;
            if (rv1 && cv1) C[(size_t)(r0c + 8) * ldc + c0c + 1] = v3;
            acc[i][j][0] = (rv0 && cv0) ? v0 : 0.f;
            acc[i][j][1] = (rv0 && cv1) ? v1 : 0.f;
            acc[i][j][2] = (rv1 && cv0) ? v2 : 0.f;
            acc[i][j][3] = (rv1 && cv1) ? v3 : 0.f;
        }
    }
    if (do_stats) {
#pragma unroll
        for (int j = 0; j < 4; j++) {
            float se = 0.f, so = 0.f, qe = 0.f, qo = 0.f;
#pragma unroll
            for (int i = 0; i < 4; i++) {
                float v0 = acc[i][j][0], v1 = acc[i][j][1];
                float v2 = acc[i][j][2], v3 = acc[i][j][3];
                se += v0 + v2; so += v1 + v3;
                qe += v0 * v0 + v2 * v2; qo += v1 * v1 + v3 * v3;
            }
#pragma unroll
            for (int off = 4; off < 32; off <<= 1) {
                se += __shfl_xor_sync(0xffffffffu, se, off);
                so += __shfl_xor_sync(0xffffffffu, so, off);
                qe += __shfl_xor_sync(0xffffffffu, qe, off);
                qo += __shfl_xor_sync(0xffffffffu, qo, off);
            }
            if (lane < 4) {
                int ce = col0 + wn * 32 + j * 8 + lane * 2;
                if (ce < Nc)     { atomicAdd(&stats[ce], se);     atomicAdd(&stats[Nc + ce], qe); }
                if (ce + 1 < Nc) { atomicAdd(&stats[ce + 1], so); atomicAdd(&stats[Nc + ce + 1], qo); }
            }
        }
    }
}

// ============ weight transpose + hi/lo convert (batched) ============
__global__ void k_wcvt(const float* __restrict__ in,
                       __nv_bfloat16* __restrict__ hi, __nv_bfloat16* __restrict__ lo,
                       int K, int N, int Kp) {
    __shared__ float t[32][33];
    int b = blockIdx.z;
    const float* I = in + (size_t)b * K * N;
    __nv_bfloat16* H = hi + (size_t)b * N * Kp;
    __nv_bfloat16* L = lo + (size_t)b * N * Kp;
    int r0 = blockIdx.y * 32, c0 = blockIdx.x * 32;
    int c = c0 + threadIdx.x;
#pragma unroll
    for (int i = 0; i < 32; i += 8) {
        int r = r0 + threadIdx.y + i;
        t[threadIdx.y + i][threadIdx.x] = (r < K && c < N) ? I[(size_t)r * N + c] : 0.f;
    }
    __syncthreads();
    int k = r0 + threadIdx.x;
#pragma unroll
    for (int i = 0; i < 32; i += 8) {
        int n = c0 + threadIdx.y + i;
        if (n < N && k < Kp) {
            float v = t[threadIdx.x][threadIdx.y + i];
            __nv_bfloat16 h, l; split_bf(v, h, l);
            H[(size_t)n * Kp + k] = h;
            L[(size_t)n * Kp + k] = l;
        }
    }
}

__global__ void k_cvtpad(const float* __restrict__ in,
                         __nv_bfloat16* __restrict__ hi, __nv_bfloat16* __restrict__ lo,
                         long total, int C, int Cp) {
    long i = (long)blockIdx.x * blockDim.x + threadIdx.x;
    if (i >= total) return;
    int n = (int)(i / Cp), c = (int)(i - (long)n * Cp);
    float v = (c < C) ? in[(size_t)n * C + c] : 0.f;
    __nv_bfloat16 h, l; split_bf(v, h, l);
    hi[i] = h; lo[i] = l;
}

__global__ void k_bnact_cvt(const float* __restrict__ X,
                            const float* __restrict__ scale, const float* __restrict__ shift,
                            __nv_bfloat16* __restrict__ hi, __nv_bfloat16* __restrict__ lo,
                            long total, int C, int Cp, int gelu) {
    long i = (long)blockIdx.x * blockDim.x + threadIdx.x;
    if (i >= total) return;
    int n = (int)(i / Cp), c = (int)(i - (long)n * Cp);
    float r = 0.f;
    if (c < C) {
        float v = X[(size_t)n * C + c] * scale[c] + shift[c];
        r = gelu ? (0.5f * v * (1.f + erff(v * 0.70710678118654752f))) : fmaxf(v, 0.f);
    }
    __nv_bfloat16 h, l; split_bf(r, h, l);
    hi[i] = h; lo[i] = l;
}

// ================= elementwise =================
__global__ void k_zero(float* p, int n) {
    int i = blockIdx.x * blockDim.x + threadIdx.x;
    if (i < n) p[i] = 0.f;
}
__global__ void k_zero_u(unsigned* p, int n) {
    int i = blockIdx.x * blockDim.x + threadIdx.x;
    if (i < n) p[i] = 0u;
}
__global__ void k_init_h4(const float4* __restrict__ atom_emb, const int* __restrict__ x_idx,
                          float4* __restrict__ h) {
    long i = (long)blockIdx.x * blockDim.x + threadIdx.x;
    const int C4 = DD / 4;
    long total = (long)NN * C4;
    if (i >= total) return;
    int n = (int)(i / C4);
    int d = (int)(i - (long)n * C4);
    h[i] = atom_emb[(size_t)x_idx[n] * C4 + d];
}
__global__ void k_init_z4(const float4* __restrict__ h, const float* __restrict__ epsp,
                          float4* __restrict__ z) {
    long i = (long)blockIdx.x * blockDim.x + threadIdx.x;
    long total = (long)NN * (DD / 4);
    if (i >= total) return;
    float e = 1.f + *epsp;
    float4 v = h[i];
    z[i] = make_float4(e * v.x, e * v.y, e * v.z, e * v.w);
}
__global__ void k_edge4(const float4* __restrict__ h, const float4* __restrict__ ee,
                        const int* __restrict__ attr, const int* __restrict__ ei,
                        float* __restrict__ z) {
    long i = (long)blockIdx.x * blockDim.x + threadIdx.x;
    const int C4 = DD / 4;
    long total = (long)EE * C4;
    if (i >= total) return;
    int e = (int)(i / C4);
    int q = (int)(i - (long)e * C4);
    int src = ei[e];
    int dst = ei[EE + e];
    float4 a = h[(size_t)src * C4 + q];
    float4 b = ee[(size_t)attr[e] * C4 + q];
    float m0 = a.x + b.x, m1 = a.y + b.y, m2 = a.z + b.z, m3 = a.w + b.w;
    float* zp = z + (size_t)dst * DD + q * 4;
    if (m0 > 0.f) atomicAdd(zp + 0, m0);
    if (m1 > 0.f) atomicAdd(zp + 1, m1);
    if (m2 > 0.f) atomicAdd(zp + 2, m2);
    if (m3 > 0.f) atomicAdd(zp + 3, m3);
}
__global__ void k_bn_final(const float* __restrict__ sums, float invM, int C,
                           const float* __restrict__ gamma, const float* __restrict__ beta,
                           float* __restrict__ scale, float* __restrict__ shift) {
    int c = blockIdx.x * blockDim.x + threadIdx.x;
    if (c >= C) return;
    float mean = sums[c] * invM;
    float var  = sums[C + c] * invM - mean * mean;
    float istd = rsqrtf(var + 1e-5f);
    float sc = istd * gamma[c];
    scale[c] = sc;
    shift[c] = beta[c] - mean * sc;
}
__global__ void k_bn_apply4(float4* __restrict__ X, float4* __restrict__ res,
                            const float4* __restrict__ scale, const float4* __restrict__ shift,
                            long total4, int C4, int mode) {
    long i = (long)blockIdx.x * blockDim.x + threadIdx.x;
    if (i >= total4) return;
    int c = (int)(i % C4);
    float4 x = X[i], sc = scale[c], sh = shift[c];
    float v0 = x.x * sc.x + sh.x, v1 = x.y * sc.y + sh.y;
    float v2 = x.z * sc.z + sh.z, v3 = x.w * sc.w + sh.w;
    float4 r = res[i];
    if (mode == 1) {
        res[i] = make_float4(r.x + fmaxf(v0, 0.f), r.y + fmaxf(v1, 0.f),
                             r.z + fmaxf(v2, 0.f), r.w + fmaxf(v3, 0.f));
    } else {
        res[i] = make_float4(r.x + v0, r.y + v1, r.z + v2, r.w + v3);
    }
}
__device__ __forceinline__ unsigned enc_f(float x) {
    unsigned u = __float_as_uint(x);
    return (u & 0x80000000u) ? ~u : (u | 0x80000000u);
}
__global__ void k_segmax(const float* __restrict__ h, const int* __restrict__ batch,
                         unsigned* __restrict__ hg) {
    long i = (long)blockIdx.x * blockDim.x + threadIdx.x;
    long total = (long)NN * DD;
    if (i >= total) return;
    int n = (int)(i / DD);
    int d = (int)(i - (long)n * DD);
    atomicMax(&hg[(size_t)batch[n] * DD + d], enc_f(h[i]));
}
__global__ void k_silu_cvt(const unsigned* __restrict__ hg,
                           __nv_bfloat16* __restrict__ hi, __nv_bfloat16* __restrict__ lo,
                           long total, int C, int Cp) {
    long i = (long)blockIdx.x * blockDim.x + threadIdx.x;
    if (i >= total) return;
    int n = (int)(i / Cp), c = (int)(i - (long)n * Cp);
    float r = 0.f;
    if (c < C) {
        unsigned u = hg[(size_t)n * C + c];
        u = (u & 0x80000000u) ? (u & 0x7fffffffu) : ~u;
        float x = __uint_as_float(u);
        r = x / (1.f + expf(-x));
    }
    __nv_bfloat16 h, l; split_bf(r, h, l);
    hi[i] = h; lo[i] = l;
}
__global__ void k_split(const float* __restrict__ d, float* __restrict__ out, long offS) {
    long i = (long)blockIdx.x * blockDim.x + threadIdx.x;
    long total = (long)GG * HH;
    if (i >= total) return;
    int g = (int)(i / HH);
    int c = (int)(i - (long)g * HH);
    float v = d[i];
    if (c < DD) {
        out[(size_t)g * DD + c] = v;
    } else {
        float sp = fmaxf(v, 0.f) + log1pf(expf(-fabsf(v))) + 1e-7f;
        out[offS + (size_t)g * DD + (c - DD)] = sp;
    }
}

// ================= host side =================
static void tgemm(const __nv_bfloat16* Ah, const __nv_bfloat16* Al, int lda,
                  const __nv_bfloat16* Bh, const __nv_bfloat16* Bl, int ldb,
                  const float* bias, float* C, int ldc,
                  int M, int Nc, int Kp, float* stats, int do_stats) {
    dim3 gr((Nc + TN - 1) / TN, (M + TM - 1) / TM);
    k_tgemm<<<gr, 256, GEMM_SMEM>>>(Ah, Al, lda, Bh, Bl, ldb, bias, C, ldc, M, Nc, Kp, stats, do_stats);
}
static void wcvt(const float* in, __nv_bfloat16* hi, __nv_bfloat16* lo,
                 int K, int N, int Kp, int B) {
    dim3 bl(32, 8), gr((N + 31) / 32, (Kp + 31) / 32, B);
    k_wcvt<<<gr, bl>>>(in, hi, lo, K, N, Kp);
}

extern "C" void kernel_launch(void* const* d_in, const int* in_sizes, int n_in,
                              void* d_out, int out_size) {
    const float* atom_emb   = (const float*)d_in[0];
    const float* edge_emb   = (const float*)d_in[1];
    const float* eps        = (const float*)d_in[2];
    const float* conv_w1    = (const float*)d_in[3];
    const float* conv_b1    = (const float*)d_in[4];
    const float* conv_bn1_g = (const float*)d_in[5];
    const float* conv_bn1_b = (const float*)d_in[6];
    const float* conv_w2    = (const float*)d_in[7];
    const float* conv_b2    = (const float*)d_in[8];
    const float* bn_g       = (const float*)d_in[9];
    const float* bn_b       = (const float*)d_in[10];
    const float* dist_w     = (const float*)d_in[11];
    const float* dist_b     = (const float*)d_in[12];
    const float* dec_w1     = (const float*)d_in[13];
    const float* dec_b1     = (const float*)d_in[14];
    const float* dec_bn_g   = (const float*)d_in[15];
    const float* dec_bn_b   = (const float*)d_in[16];
    const float* dec_w2     = (const float*)d_in[17];
    const float* dec_b2     = (const float*)d_in[18];
    const int*   x_idx      = (const int*)d_in[19];
    const int*   edge_attr  = (const int*)d_in[20];
    const int*   edge_index = (const int*)d_in[21];
    const int*   batch      = (const int*)d_in[22];
    float* out = (float*)d_out;

    cudaFuncSetAttribute(k_tgemm, cudaFuncAttributeMaxDynamicSharedMemorySize, GEMM_SMEM);

    float *h, *z, *y, *stats, *scale, *shift, *dbuf, *dz;
    unsigned* hg;
    __nv_bfloat16 *zh, *zl, *yh, *yl, *sh, *sl, *muh, *mul, *dzh, *dzl;
    __nv_bfloat16 *w1th, *w1tl, *w2th, *w2tl, *dwth, *dwtl, *d1th, *d1tl, *d2th, *d2tl;
    cudaGetSymbolAddress((void**)&h,     g_h);
    cudaGetSymbolAddress((void**)&z,     g_z);
    cudaGetSymbolAddress((void**)&y,     g_y);
    cudaGetSymbolAddress((void**)&stats, g_stats);
    cudaGetSymbolAddress((void**)&scale, g_scale);
    cudaGetSymbolAddress((void**)&shift, g_shift);
    cudaGetSymbolAddress((void**)&hg,    g_hg);
    cudaGetSymbolAddress((void**)&dbuf,  g_d);
    cudaGetSymbolAddress((void**)&dz,    g_dz);
    cudaGetSymbolAddress((void**)&zh,    g_zh);   cudaGetSymbolAddress((void**)&zl,  g_zl);
    cudaGetSymbolAddress((void**)&yh,    g_yh);   cudaGetSymbolAddress((void**)&yl,  g_yl);
    cudaGetSymbolAddress((void**)&sh,    g_sh);   cudaGetSymbolAddress((void**)&sl,  g_sl);
    cudaGetSymbolAddress((void**)&muh,   g_muh);  cudaGetSymbolAddress((void**)&mul, g_mul);
    cudaGetSymbolAddress((void**)&dzh,   g_dzh);  cudaGetSymbolAddress((void**)&dzl, g_dzl);
    cudaGetSymbolAddress((void**)&w1th,  g_w1th); cudaGetSymbolAddress((void**)&w1tl, g_w1tl);
    cudaGetSymbolAddress((void**)&w2th,  g_w2th); cudaGetSymbolAddress((void**)&w2tl, g_w2tl);
    cudaGetSymbolAddress((void**)&dwth,  g_dwth); cudaGetSymbolAddress((void**)&dwtl, g_dwtl);
    cudaGetSymbolAddress((void**)&d1th,  g_d1th); cudaGetSymbolAddress((void**)&d1tl, g_d1tl);
    cudaGetSymbolAddress((void**)&d2th,  g_d2th); cudaGetSymbolAddress((void**)&d2tl, g_d2tl);

    // transpose + convert weights once per call
    wcvt(conv_w1, w1th, w1tl, DD, HH, KPD, LL);
    wcvt(conv_w2, w2th, w2tl, HH, DD, KPH, LL);
    wcvt(dist_w,  dwth, dwtl, DD, HH, KPD, 1);
    wcvt(dec_w1,  d1th, d1tl, DD, DECH, KPD, 6);
    wcvt(dec_w2,  d2th, d2tl, DECH, MAXO, KPDEC, 6);

    const long ND  = (long)NN * DD;
    const long ND4 = ND / 4;
    const long ED4 = (long)EE * DD / 4;
    const long NZP = (long)NN * KPD;
    const long NYP = (long)NN * KPH;

    k_init_h4<<<(int)((ND4 + 255) / 256), 256>>>((const float4*)atom_emb, x_idx, (float4*)h);

    for (int l = 0; l < LL; l++) {
        k_init_z4<<<(int)((ND4 + 255) / 256), 256>>>((const float4*)h, eps + l, (float4*)z);
        k_edge4<<<(int)((ED4 + 255) / 256), 256>>>((const float4*)h,
                 (const float4*)(edge_emb + (size_t)l * 5 * DD), edge_attr, edge_index, z);
        k_cvtpad<<<(int)((NZP + 255) / 256), 256>>>(z, zh, zl, NZP, DD, KPD);
        k_zero<<<(2 * HH + 255) / 256, 256>>>(stats, 2 * HH);
        tgemm(zh, zl, KPD, w1th + (size_t)l * HH * KPD, w1tl + (size_t)l * HH * KPD, KPD,
              conv_b1 + (size_t)l * HH, y, HH, NN, HH, KPD, stats, 1);
        k_bn_final<<<(HH + 255) / 256, 256>>>(stats, 1.f / (float)NN, HH,
              conv_bn1_g + (size_t)l * HH, conv_bn1_b + (size_t)l * HH, scale, shift);
        k_bnact_cvt<<<(int)((NYP + 255) / 256), 256>>>(y, scale, shift, yh, yl, NYP, HH, KPH, 0);
        k_zero<<<(2 * DD + 255) / 256, 256>>>(stats, 2 * DD);
        tgemm(yh, yl, KPH, w2th + (size_t)l * DD * KPH, w2tl + (size_t)l * DD * KPH, KPH,
              conv_b2 + (size_t)l * DD, z, DD, NN, DD, KPH, stats, 1);
        k_bn_final<<<(DD + 255) / 256, 256>>>(stats, 1.f / (float)NN, DD,
              bn_g + (size_t)l * DD, bn_b + (size_t)l * DD, scale, shift);
        k_bn_apply4<<<(int)((ND4 + 255) / 256), 256>>>((float4*)z, (float4*)h,
              (const float4*)scale, (const float4*)shift, ND4, DD / 4, (l < LL - 1) ? 1 : 2);
    }

    // pooling -> silu -> bf16
    int GD = GG * DD;
    const long GSP = (long)GG * KPD;
    k_zero_u<<<(GD + 255) / 256, 256>>>(hg, GD);
    k_segmax<<<(int)((ND + 255) / 256), 256>>>(h, batch, hg);
    k_silu_cvt<<<(int)((GSP + 255) / 256), 256>>>(hg, sh, sl, GSP, DD, KPD);

    // d = silu(h_graph) @ dist_w + dist_b
    tgemm(sh, sl, KPD, dwth, dwtl, KPD, dist_b, dbuf, HH, GG, HH, KPD, stats, 0);

    const long OFF_SG = (long)GG * DD;
    k_split<<<(int)(((long)GG * HH + 255) / 256), 256>>>(dbuf, out, OFF_SG);
    k_cvtpad<<<(int)((GSP + 255) / 256), 256>>>(out, muh, mul, GSP, DD, KPD);

    const long OFF_O0   = 2L * GG * DD;
    const long OFF_GENE = OFF_O0 + (long)GG * 1024;
    const long OFF_CELL = OFF_GENE + (long)GG * 1973;
    const long OFF_O5   = OFF_CELL + (long)GG * 2749;
    const int  dims[6] = {1024, 1111, 862, 1783, 966, 978};
    const long base[6] = {OFF_O0, OFF_GENE, OFF_GENE + 1111, OFF_CELL, OFF_CELL + 1783, OFF_O5};
    const int  ldcs[6] = {1024, 1973, 1973, 2749, 2749, 978};

    const long GDP = (long)GG * KPDEC;
    for (int i = 0; i < 6; i++) {
        k_zero<<<(2 * DECH + 255) / 256, 256>>>(stats, 2 * DECH);
        tgemm(muh, mul, KPD, d1th + (size_t)i * DECH * KPD, d1tl + (size_t)i * DECH * KPD, KPD,
              dec_b1 + (size_t)i * DECH, dz, DECH, GG, DECH, KPD, stats, 1);
        k_bn_final<<<(DECH + 255) / 256, 256>>>(stats, 1.f / (float)GG, DECH,
              dec_bn_g + (size_t)i * DECH, dec_bn_b + (size_t)i * DECH, scale, shift);
        k_bnact_cvt<<<(int)((GDP + 255) / 256), 256>>>(dz, scale, shift, dzh, dzl, GDP, DECH, KPDEC, 1);
        tgemm(dzh, dzl, KPDEC, d2th + (size_t)i * MAXO * KPDEC, d2tl + (size_t)i * MAXO * KPDEC, KPDEC,
              dec_b2 + (size_t)i * MAXO, out + base[i], ldcs[i], GG, dims[i], KPDEC, stats, 0);
    }
}